// round 6
// baseline (speedup 1.0000x reference)
#include <cuda_runtime.h>

// ---------------------------------------------------------------------------
// Problem constants
// ---------------------------------------------------------------------------
#define B_ROWS 32768
#define D_IN   1024
#define H_DIM  512
#define L_DIM  64
#define NBL    (B_ROWS * L_DIM)   // 2097152

// Scratch (allocation-free rule: __device__ globals)
__device__ float g_h1[(size_t)B_ROWS * H_DIM];
__device__ float g_h2[(size_t)B_ROWS * H_DIM];

// Accurate libdevice entry points (immune to -use_fast_math remapping)
extern "C" {
__device__ float __nv_logf(float);
__device__ float __nv_log1pf(float);
__device__ float __nv_expf(float);
}

// ---------------------------------------------------------------------------
// f32x2 packed-FMA helpers (sm_100+: fma.rn.f32x2, 2 fp32 FMAs / instruction)
// ---------------------------------------------------------------------------
__device__ __forceinline__ unsigned long long pack2(float lo, float hi) {
    unsigned long long r;
    asm("mov.b64 %0, {%1, %2};" : "=l"(r) : "f"(lo), "f"(hi));
    return r;
}
__device__ __forceinline__ void unpack2(unsigned long long v, float &lo, float &hi) {
    asm("mov.b64 {%0, %1}, %2;" : "=f"(lo), "=f"(hi) : "l"(v));
}
__device__ __forceinline__ unsigned long long fma2(unsigned long long a,
                                                   unsigned long long b,
                                                   unsigned long long c) {
    unsigned long long r;
    asm("fma.rn.f32x2 %0, %1, %2, %3;" : "=l"(r) : "l"(a), "l"(b), "l"(c));
    return r;
}

// ---------------------------------------------------------------------------
// threefry2x32 (JAX-exact, 20 rounds)
// ---------------------------------------------------------------------------
__host__ __device__ __forceinline__ void tf2x32(unsigned int k0, unsigned int k1,
                                                unsigned int x0, unsigned int x1,
                                                unsigned int &o0, unsigned int &o1) {
    unsigned int ks2 = k0 ^ k1 ^ 0x1BD11BDAu;
    x0 += k0; x1 += k1;
#define TF_R(r) { x0 += x1; x1 = (x1 << (r)) | (x1 >> (32 - (r))); x1 ^= x0; }
    TF_R(13) TF_R(15) TF_R(26) TF_R(6)
    x0 += k1;  x1 += ks2 + 1u;
    TF_R(17) TF_R(29) TF_R(16) TF_R(24)
    x0 += ks2; x1 += k0 + 2u;
    TF_R(13) TF_R(15) TF_R(26) TF_R(6)
    x0 += k0;  x1 += k1 + 3u;
    TF_R(17) TF_R(29) TF_R(16) TF_R(24)
    x0 += k1;  x1 += ks2 + 4u;
    TF_R(13) TF_R(15) TF_R(26) TF_R(6)
    x0 += ks2; x1 += k0 + 5u;
#undef TF_R
    o0 = x0; o1 = x1;
}

// ---------------------------------------------------------------------------
// XLA ErfInv (Giles rational approximation, fp32, unfused to mirror XLA)
// ---------------------------------------------------------------------------
__device__ __forceinline__ float erfinv_xla(float x) {
    float w = -__nv_log1pf(-__fmul_rn(x, x));
    float p;
    if (w < 5.0f) {
        w = __fsub_rn(w, 2.5f);
        p = 2.81022636e-08f;
        p = __fadd_rn(__fmul_rn(p, w), 3.43273939e-07f);
        p = __fadd_rn(__fmul_rn(p, w), -3.5233877e-06f);
        p = __fadd_rn(__fmul_rn(p, w), -4.39150654e-06f);
        p = __fadd_rn(__fmul_rn(p, w), 0.00021858087f);
        p = __fadd_rn(__fmul_rn(p, w), -0.00125372503f);
        p = __fadd_rn(__fmul_rn(p, w), -0.00417768164f);
        p = __fadd_rn(__fmul_rn(p, w), 0.246640727f);
        p = __fadd_rn(__fmul_rn(p, w), 1.50140941f);
    } else {
        w = __fsub_rn(__fsqrt_rn(w), 3.0f);
        p = -0.000200214257f;
        p = __fadd_rn(__fmul_rn(p, w), 0.000100950558f);
        p = __fadd_rn(__fmul_rn(p, w), 0.00134934322f);
        p = __fadd_rn(__fmul_rn(p, w), -0.00367342844f);
        p = __fadd_rn(__fmul_rn(p, w), 0.00573950773f);
        p = __fadd_rn(__fmul_rn(p, w), -0.0076224613f);
        p = __fadd_rn(__fmul_rn(p, w), 0.00943887047f);
        p = __fadd_rn(__fmul_rn(p, w), 1.00167406f);
        p = __fadd_rn(__fmul_rn(p, w), 2.83297682f);
    }
    return __fmul_rn(p, x);
}

// ---------------------------------------------------------------------------
// Tiled SIMT fp32 GEMM, C = act(A[M,K] @ B[K,N] + bias), f32x2 accumulators.
// ACT: 1 = relu, 2 = softplus(x)+0.5
// ---------------------------------------------------------------------------
template <int BM, int BN, int BK, int TM, int TN, int ACT>
__global__ void __launch_bounds__((BM / TM) * (BN / TN))
gemm_act(const float *__restrict__ A, const float *__restrict__ Bw,
         const float *__restrict__ bias, float *__restrict__ C,
         int K, int N) {
    constexpr int THREADS = (BM / TM) * (BN / TN);
    constexpr int TNH = TN / 2;
    const int tid  = threadIdx.x;
    const int tx   = tid % (BN / TN);
    const int ty   = tid / (BN / TN);
    const int row0 = blockIdx.y * BM;
    const int col0 = blockIdx.x * BN;

    __shared__ __align__(16) float As[2][BK][BM];
    __shared__ __align__(16) float Bs[2][BK][BN];

    const float *Ag = A + (size_t)row0 * K;
    const float *Bg = Bw + col0;

    constexpr int A_LD_ITERS = (BM * BK) / (4 * THREADS);
    constexpr int B_LD_ITERS = (BK * BN) / (4 * THREADS);

    unsigned long long acc[TM][TNH];
#pragma unroll
    for (int i = 0; i < TM; i++)
#pragma unroll
        for (int j = 0; j < TNH; j++) acc[i][j] = 0ull;

    auto loadA = [&](int buf, int k0) {
#pragma unroll
        for (int i = 0; i < A_LD_ITERS; i++) {
            int idx = tid + i * THREADS;
            int r   = idx / (BK / 4);
            int c4  = idx % (BK / 4);
            float4 v = *(const float4 *)(Ag + (size_t)r * K + k0 + c4 * 4);
            As[buf][c4 * 4 + 0][r] = v.x;
            As[buf][c4 * 4 + 1][r] = v.y;
            As[buf][c4 * 4 + 2][r] = v.z;
            As[buf][c4 * 4 + 3][r] = v.w;
        }
    };
    auto loadB = [&](int buf, int k0) {
#pragma unroll
        for (int i = 0; i < B_LD_ITERS; i++) {
            int idx = tid + i * THREADS;
            int r   = idx / (BN / 4);
            int c4  = idx % (BN / 4);
            *(float4 *)&Bs[buf][r][c4 * 4] =
                *(const float4 *)(Bg + (size_t)(k0 + r) * N + c4 * 4);
        }
    };

    loadA(0, 0);
    loadB(0, 0);
    __syncthreads();

    const int nk = K / BK;
    for (int kt = 0; kt < nk; ++kt) {
        const int buf = kt & 1;
        if (kt + 1 < nk) {            // prefetch next tile into other buffer
            loadA(buf ^ 1, (kt + 1) * BK);
            loadB(buf ^ 1, (kt + 1) * BK);
        }
#pragma unroll
        for (int k = 0; k < BK; k++) {
            float a[TM];
#pragma unroll
            for (int i = 0; i < TM; i += 4) {
                float4 v = *(const float4 *)&As[buf][k][ty * TM + i];
                a[i] = v.x; a[i + 1] = v.y; a[i + 2] = v.z; a[i + 3] = v.w;
            }
            unsigned long long bp[TNH];
#pragma unroll
            for (int j = 0; j < TNH; j += 2) {
                ulonglong2 bv = *(const ulonglong2 *)&Bs[buf][k][tx * TN + 2 * j];
                bp[j] = bv.x; bp[j + 1] = bv.y;
            }
#pragma unroll
            for (int i = 0; i < TM; i++) {
                unsigned long long ad = pack2(a[i], a[i]);
#pragma unroll
                for (int j = 0; j < TNH; j++) acc[i][j] = fma2(ad, bp[j], acc[i][j]);
            }
        }
        __syncthreads();
    }

    // epilogue
    float bch[TN];
#pragma unroll
    for (int j = 0; j < TN; j++) bch[j] = bias[col0 + tx * TN + j];

#pragma unroll
    for (int i = 0; i < TM; i++) {
        float outv[TN];
#pragma unroll
        for (int j = 0; j < TNH; j++) unpack2(acc[i][j], outv[2 * j], outv[2 * j + 1]);
#pragma unroll
        for (int j = 0; j < TN; j++) {
            float v = outv[j] + bch[j];
            if (ACT == 1) {
                v = fmaxf(v, 0.0f);
            } else if (ACT == 2) {
                // softplus(x) = max(x,0) + log1p(exp(-|x|)); then +0.5
                v = fmaxf(v, 0.0f) + __nv_log1pf(__nv_expf(-fabsf(v))) + 0.5f;
            }
            outv[j] = v;
        }
        float *cp = C + (size_t)(row0 + ty * TM + i) * N + col0 + tx * TN;
#pragma unroll
        for (int j = 0; j < TN; j += 4)
            *(float4 *)(cp + j) = make_float4(outv[j], outv[j + 1], outv[j + 2], outv[j + 3]);
    }
}

// ---------------------------------------------------------------------------
// Marsaglia-Tsang sampler, JAX-exact randomness (threefry_partitionable).
// bits(k,b,l) = o0 ^ o1 of threefry2x32(key, (0, k*NBL + b*L + l)).
// Lazy rejection: only evaluates proposal k when k-1 was rejected.
// ---------------------------------------------------------------------------
__global__ void __launch_bounds__(256)
sampler_kernel(const float *__restrict__ alpha, float *__restrict__ outp,
               unsigned int kz0, unsigned int kz1,
               unsigned int ku0, unsigned int ku1) {
    int idx = blockIdx.x * 256 + threadIdx.x;
    if (idx >= NBL) return;

    const float LO = -0.99999994f;   // nextafterf(-1, 0)

    float a = alpha[idx];
    float d = __fsub_rn(a, 0.33333334f);                               // alpha - 1/3
    float c = __fdiv_rn(1.0f, __fsqrt_rn(__fmul_rn(9.0f, d)));         // 1/sqrt(9d)

    float result = 0.0f, first_s = 0.0f;
    bool done = false;

#pragma unroll 1
    for (int k = 0; k < 16; ++k) {
        unsigned int cnt = (unsigned int)(k * NBL + idx);

        // z ~ normal(kz): sqrt(2)*erfinv(uniform(lo=nextafter(-1,0), hi=1))
        unsigned int o0, o1;
        tf2x32(kz0, kz1, 0u, cnt, o0, o1);
        unsigned int bz = o0 ^ o1;
        float fz = __fsub_rn(__uint_as_float((bz >> 9) | 0x3f800000u), 1.0f);
        float un = fmaxf(LO, __fadd_rn(__fmul_rn(fz, 2.0f), LO));      // (hi-lo) folds to 2.0f
        float z  = __fmul_rn(1.41421356f, erfinv_xla(un));

        // v = (1 + c*z)^3
        float t  = __fadd_rn(1.0f, __fmul_rn(c, z));
        float v  = __fmul_rn(__fmul_rn(t, t), t);
        bool pos = v > 0.0f;
        float sv = pos ? v : 1.0f;
        float samp = __fmul_rn(d, sv);
        if (k == 0) first_s = samp;

        // u ~ uniform(ku, 1e-7, 1)
        tf2x32(ku0, ku1, 0u, cnt, o0, o1);
        unsigned int bu = o0 ^ o1;
        float fu = __fsub_rn(__uint_as_float((bu >> 9) | 0x3f800000u), 1.0f);
        float uu = fmaxf(1e-7f, __fadd_rn(__fmul_rn(fu, (1.0f - 1e-7f)), 1e-7f));

        // b2 = 0.5*z^2 + d - d*sv + d*log(sv)
        float zz = __fmul_rn(z, z);
        float b2 = __fadd_rn(
            __fsub_rn(__fadd_rn(__fmul_rn(0.5f, zz), d), __fmul_rn(d, sv)),
            __fmul_rn(d, __nv_logf(sv)));

        if (pos && (__nv_logf(uu) < b2)) { result = samp; done = true; break; }
    }
    outp[idx] = done ? result : first_s;   // argmax of all-false selects index 0
}

// ---------------------------------------------------------------------------
// Launch
// ---------------------------------------------------------------------------
extern "C" void kernel_launch(void *const *d_in, const int *in_sizes, int n_in,
                              void *d_out, int out_size) {
    const float *x  = (const float *)d_in[0];
    const float *W0 = (const float *)d_in[1];
    const float *b0 = (const float *)d_in[2];
    const float *W1 = (const float *)d_in[3];
    const float *b1 = (const float *)d_in[4];
    const float *Wl = (const float *)d_in[5];
    const float *bl = (const float *)d_in[6];
    float *out = (float *)d_out;           // [alpha (B*L) | sample (B*L)]

    float *h1, *h2;
    cudaGetSymbolAddress((void **)&h1, g_h1);
    cudaGetSymbolAddress((void **)&h2, g_h2);

    dim3 g1(H_DIM / 128, B_ROWS / 128);
    gemm_act<128, 128, 16, 8, 8, 1><<<g1, 256>>>(x,  W0, b0, h1, D_IN,  H_DIM);
    gemm_act<128, 128, 16, 8, 8, 1><<<g1, 256>>>(h1, W1, b1, h2, H_DIM, H_DIM);

    dim3 g3(L_DIM / 64, B_ROWS / 128);
    gemm_act<128, 64, 16, 8, 4, 2><<<g3, 256>>>(h2, Wl, bl, out, H_DIM, L_DIM);

    // fold-like split of key(1) = (0,1): kz = cipher(key;0,0), ku = cipher(key;0,1)
    unsigned int kz0, kz1, ku0, ku1;
    tf2x32(0u, 1u, 0u, 0u, kz0, kz1);
    tf2x32(0u, 1u, 0u, 1u, ku0, ku1);

    sampler_kernel<<<NBL / 256, 256>>>(out, out + NBL, kz0, kz1, ku0, ku1);
}

// round 7
// speedup vs baseline: 1.0543x; 1.0543x over previous
#include <cuda_runtime.h>

// ---------------------------------------------------------------------------
// Problem constants
// ---------------------------------------------------------------------------
#define B_ROWS 32768
#define D_IN   1024
#define H_DIM  512
#define L_DIM  64
#define NBL    (B_ROWS * L_DIM)   // 2097152

// Scratch (allocation-free rule: __device__ globals)
__device__ float g_h1[(size_t)B_ROWS * H_DIM];
__device__ float g_h2[(size_t)B_ROWS * H_DIM];

// Accurate libdevice entry points (immune to -use_fast_math remapping)
extern "C" {
__device__ float __nv_logf(float);
__device__ float __nv_log1pf(float);
__device__ float __nv_expf(float);
}

// ---------------------------------------------------------------------------
// f32x2 packed-FMA helpers (sm_100+: fma.rn.f32x2, 2 fp32 FMAs / instruction)
// ---------------------------------------------------------------------------
__device__ __forceinline__ unsigned long long pack2(float lo, float hi) {
    unsigned long long r;
    asm("mov.b64 %0, {%1, %2};" : "=l"(r) : "f"(lo), "f"(hi));
    return r;
}
__device__ __forceinline__ void unpack2(unsigned long long v, float &lo, float &hi) {
    asm("mov.b64 {%0, %1}, %2;" : "=f"(lo), "=f"(hi) : "l"(v));
}
__device__ __forceinline__ unsigned long long fma2(unsigned long long a,
                                                   unsigned long long b,
                                                   unsigned long long c) {
    unsigned long long r;
    asm("fma.rn.f32x2 %0, %1, %2, %3;" : "=l"(r) : "l"(a), "l"(b), "l"(c));
    return r;
}

// ---------------------------------------------------------------------------
// threefry2x32 (JAX-exact, 20 rounds)
// ---------------------------------------------------------------------------
__host__ __device__ __forceinline__ void tf2x32(unsigned int k0, unsigned int k1,
                                                unsigned int x0, unsigned int x1,
                                                unsigned int &o0, unsigned int &o1) {
    unsigned int ks2 = k0 ^ k1 ^ 0x1BD11BDAu;
    x0 += k0; x1 += k1;
#define TF_R(r) { x0 += x1; x1 = (x1 << (r)) | (x1 >> (32 - (r))); x1 ^= x0; }
    TF_R(13) TF_R(15) TF_R(26) TF_R(6)
    x0 += k1;  x1 += ks2 + 1u;
    TF_R(17) TF_R(29) TF_R(16) TF_R(24)
    x0 += ks2; x1 += k0 + 2u;
    TF_R(13) TF_R(15) TF_R(26) TF_R(6)
    x0 += k0;  x1 += k1 + 3u;
    TF_R(17) TF_R(29) TF_R(16) TF_R(24)
    x0 += k1;  x1 += ks2 + 4u;
    TF_R(13) TF_R(15) TF_R(26) TF_R(6)
    x0 += ks2; x1 += k0 + 5u;
#undef TF_R
    o0 = x0; o1 = x1;
}

// ---------------------------------------------------------------------------
// XLA ErfInv (Giles rational approximation, fp32, unfused to mirror XLA)
// ---------------------------------------------------------------------------
__device__ __forceinline__ float erfinv_xla(float x) {
    float w = -__nv_log1pf(-__fmul_rn(x, x));
    float p;
    if (w < 5.0f) {
        w = __fsub_rn(w, 2.5f);
        p = 2.81022636e-08f;
        p = __fadd_rn(__fmul_rn(p, w), 3.43273939e-07f);
        p = __fadd_rn(__fmul_rn(p, w), -3.5233877e-06f);
        p = __fadd_rn(__fmul_rn(p, w), -4.39150654e-06f);
        p = __fadd_rn(__fmul_rn(p, w), 0.00021858087f);
        p = __fadd_rn(__fmul_rn(p, w), -0.00125372503f);
        p = __fadd_rn(__fmul_rn(p, w), -0.00417768164f);
        p = __fadd_rn(__fmul_rn(p, w), 0.246640727f);
        p = __fadd_rn(__fmul_rn(p, w), 1.50140941f);
    } else {
        w = __fsub_rn(__fsqrt_rn(w), 3.0f);
        p = -0.000200214257f;
        p = __fadd_rn(__fmul_rn(p, w), 0.000100950558f);
        p = __fadd_rn(__fmul_rn(p, w), 0.00134934322f);
        p = __fadd_rn(__fmul_rn(p, w), -0.00367342844f);
        p = __fadd_rn(__fmul_rn(p, w), 0.00573950773f);
        p = __fadd_rn(__fmul_rn(p, w), -0.0076224613f);
        p = __fadd_rn(__fmul_rn(p, w), 0.00943887047f);
        p = __fadd_rn(__fmul_rn(p, w), 1.00167406f);
        p = __fadd_rn(__fmul_rn(p, w), 2.83297682f);
    }
    return __fmul_rn(p, x);
}

// ---------------------------------------------------------------------------
// Tiled SIMT fp32 GEMM, C = act(A[M,K] @ B[K,N] + bias), f32x2 accumulators.
// ACT: 1 = relu, 2 = softplus(x)+0.5
// ---------------------------------------------------------------------------
template <int BM, int BN, int BK, int TM, int TN, int ACT>
__global__ void __launch_bounds__((BM / TM) * (BN / TN))
gemm_act(const float *__restrict__ A, const float *__restrict__ Bw,
         const float *__restrict__ bias, float *__restrict__ C,
         int K, int N) {
    constexpr int THREADS = (BM / TM) * (BN / TN);
    constexpr int TNH = TN / 2;
    const int tid  = threadIdx.x;
    const int tx   = tid % (BN / TN);
    const int ty   = tid / (BN / TN);
    const int row0 = blockIdx.y * BM;
    const int col0 = blockIdx.x * BN;

    __shared__ __align__(16) float As[2][BK][BM];
    __shared__ __align__(16) float Bs[2][BK][BN];

    const float *Ag = A + (size_t)row0 * K;
    const float *Bg = Bw + col0;

    constexpr int A_LD_ITERS = (BM * BK) / (4 * THREADS);
    constexpr int B_LD_ITERS = (BK * BN) / (4 * THREADS);

    unsigned long long acc[TM][TNH];
#pragma unroll
    for (int i = 0; i < TM; i++)
#pragma unroll
        for (int j = 0; j < TNH; j++) acc[i][j] = 0ull;

    auto loadA = [&](int buf, int k0) {
#pragma unroll
        for (int i = 0; i < A_LD_ITERS; i++) {
            int idx = tid + i * THREADS;
            int r   = idx / (BK / 4);
            int c4  = idx % (BK / 4);
            float4 v = *(const float4 *)(Ag + (size_t)r * K + k0 + c4 * 4);
            As[buf][c4 * 4 + 0][r] = v.x;
            As[buf][c4 * 4 + 1][r] = v.y;
            As[buf][c4 * 4 + 2][r] = v.z;
            As[buf][c4 * 4 + 3][r] = v.w;
        }
    };
    auto loadB = [&](int buf, int k0) {
#pragma unroll
        for (int i = 0; i < B_LD_ITERS; i++) {
            int idx = tid + i * THREADS;
            int r   = idx / (BN / 4);
            int c4  = idx % (BN / 4);
            *(float4 *)&Bs[buf][r][c4 * 4] =
                *(const float4 *)(Bg + (size_t)(k0 + r) * N + c4 * 4);
        }
    };

    loadA(0, 0);
    loadB(0, 0);
    __syncthreads();

    const int nk = K / BK;
    for (int kt = 0; kt < nk; ++kt) {
        const int buf = kt & 1;
        if (kt + 1 < nk) {            // prefetch next tile into other buffer
            loadA(buf ^ 1, (kt + 1) * BK);
            loadB(buf ^ 1, (kt + 1) * BK);
        }
#pragma unroll
        for (int k = 0; k < BK; k++) {
            float a[TM];
#pragma unroll
            for (int i = 0; i < TM; i += 4) {
                float4 v = *(const float4 *)&As[buf][k][ty * TM + i];
                a[i] = v.x; a[i + 1] = v.y; a[i + 2] = v.z; a[i + 3] = v.w;
            }
            unsigned long long bp[TNH];
#pragma unroll
            for (int j = 0; j < TNH; j += 2) {
                ulonglong2 bv = *(const ulonglong2 *)&Bs[buf][k][tx * TN + 2 * j];
                bp[j] = bv.x; bp[j + 1] = bv.y;
            }
#pragma unroll
            for (int i = 0; i < TM; i++) {
                unsigned long long ad = pack2(a[i], a[i]);
#pragma unroll
                for (int j = 0; j < TNH; j++) acc[i][j] = fma2(ad, bp[j], acc[i][j]);
            }
        }
        __syncthreads();
    }

    // epilogue
    float bch[TN];
#pragma unroll
    for (int j = 0; j < TN; j++) bch[j] = bias[col0 + tx * TN + j];

#pragma unroll
    for (int i = 0; i < TM; i++) {
        float outv[TN];
#pragma unroll
        for (int j = 0; j < TNH; j++) unpack2(acc[i][j], outv[2 * j], outv[2 * j + 1]);
#pragma unroll
        for (int j = 0; j < TN; j++) {
            float v = outv[j] + bch[j];
            if (ACT == 1) {
                v = fmaxf(v, 0.0f);
            } else if (ACT == 2) {
                // softplus(x) = max(x,0) + log1p(exp(-|x|)); then +0.5
                v = fmaxf(v, 0.0f) + __nv_log1pf(__nv_expf(-fabsf(v))) + 0.5f;
            }
            outv[j] = v;
        }
        float *cp = C + (size_t)(row0 + ty * TM + i) * N + col0 + tx * TN;
#pragma unroll
        for (int j = 0; j < TN; j += 4)
            *(float4 *)(cp + j) = make_float4(outv[j], outv[j + 1], outv[j + 2], outv[j + 3]);
    }
}

// ---------------------------------------------------------------------------
// Marsaglia-Tsang sampler, JAX-exact randomness (threefry_partitionable).
// bits(k,b,l) = o0 ^ o1 of threefry2x32(key, (0, k*NBL + b*L + l)).
// Lazy rejection: only evaluates proposal k when k-1 was rejected.
// ---------------------------------------------------------------------------
__global__ void __launch_bounds__(256)
sampler_kernel(const float *__restrict__ alpha, float *__restrict__ outp,
               unsigned int kz0, unsigned int kz1,
               unsigned int ku0, unsigned int ku1) {
    int idx = blockIdx.x * 256 + threadIdx.x;
    if (idx >= NBL) return;

    const float LO = -0.99999994f;   // nextafterf(-1, 0)

    float a = alpha[idx];
    float d = __fsub_rn(a, 0.33333334f);                               // alpha - 1/3
    float c = __fdiv_rn(1.0f, __fsqrt_rn(__fmul_rn(9.0f, d)));         // 1/sqrt(9d)

    float result = 0.0f, first_s = 0.0f;
    bool done = false;

#pragma unroll 1
    for (int k = 0; k < 16; ++k) {
        unsigned int cnt = (unsigned int)(k * NBL + idx);

        // z ~ normal(kz): sqrt(2)*erfinv(uniform(lo=nextafter(-1,0), hi=1))
        unsigned int o0, o1;
        tf2x32(kz0, kz1, 0u, cnt, o0, o1);
        unsigned int bz = o0 ^ o1;
        float fz = __fsub_rn(__uint_as_float((bz >> 9) | 0x3f800000u), 1.0f);
        float un = fmaxf(LO, __fadd_rn(__fmul_rn(fz, 2.0f), LO));      // (hi-lo) folds to 2.0f
        float z  = __fmul_rn(1.41421356f, erfinv_xla(un));

        // v = (1 + c*z)^3
        float t  = __fadd_rn(1.0f, __fmul_rn(c, z));
        float v  = __fmul_rn(__fmul_rn(t, t), t);
        bool pos = v > 0.0f;
        float sv = pos ? v : 1.0f;
        float samp = __fmul_rn(d, sv);
        if (k == 0) first_s = samp;

        // u ~ uniform(ku, 1e-7, 1)
        tf2x32(ku0, ku1, 0u, cnt, o0, o1);
        unsigned int bu = o0 ^ o1;
        float fu = __fsub_rn(__uint_as_float((bu >> 9) | 0x3f800000u), 1.0f);
        float uu = fmaxf(1e-7f, __fadd_rn(__fmul_rn(fu, (1.0f - 1e-7f)), 1e-7f));

        // b2 = 0.5*z^2 + d - d*sv + d*log(sv)
        float zz = __fmul_rn(z, z);
        float b2 = __fadd_rn(
            __fsub_rn(__fadd_rn(__fmul_rn(0.5f, zz), d), __fmul_rn(d, sv)),
            __fmul_rn(d, __nv_logf(sv)));

        if (pos && (__nv_logf(uu) < b2)) { result = samp; done = true; break; }
    }
    outp[idx] = done ? result : first_s;   // argmax of all-false selects index 0
}

// ---------------------------------------------------------------------------
// Launch
// ---------------------------------------------------------------------------
extern "C" void kernel_launch(void *const *d_in, const int *in_sizes, int n_in,
                              void *d_out, int out_size) {
    const float *x  = (const float *)d_in[0];
    const float *W0 = (const float *)d_in[1];
    const float *b0 = (const float *)d_in[2];
    const float *W1 = (const float *)d_in[3];
    const float *b1 = (const float *)d_in[4];
    const float *Wl = (const float *)d_in[5];
    const float *bl = (const float *)d_in[6];
    float *out = (float *)d_out;           // [alpha (B*L) | sample (B*L)]

    float *h1, *h2;
    cudaGetSymbolAddress((void **)&h1, g_h1);
    cudaGetSymbolAddress((void **)&h2, g_h2);

    dim3 g1(H_DIM / 128, B_ROWS / 128);
    gemm_act<128, 128, 16, 8, 8, 1><<<g1, 256>>>(x,  W0, b0, h1, D_IN,  H_DIM);
    gemm_act<128, 128, 16, 8, 8, 1><<<g1, 256>>>(h1, W1, b1, h2, H_DIM, H_DIM);

    dim3 g3(L_DIM / 64, B_ROWS / 128);
    gemm_act<128, 64, 16, 8, 4, 2><<<g3, 256>>>(h2, Wl, bl, out, H_DIM, L_DIM);

    // fold-like split of key(1) = (0,1): kz = cipher(key;0,0), ku = cipher(key;0,1)
    unsigned int kz0, kz1, ku0, ku1;
    tf2x32(0u, 1u, 0u, 0u, kz0, kz1);
    tf2x32(0u, 1u, 0u, 1u, ku0, ku1);

    sampler_kernel<<<NBL / 256, 256>>>(out, out + NBL, kz0, kz1, ku0, ku1);
}

// round 16
// speedup vs baseline: 1.4010x; 1.3288x over previous
#include <cuda_runtime.h>
#include <cuda_bf16.h>

// ---------------------------------------------------------------------------
// Problem constants
// ---------------------------------------------------------------------------
#define B_ROWS 32768
#define D_IN   1024
#define H_DIM  512
#define L_DIM  64
#define NBL    (B_ROWS * L_DIM)   // 2097152

// Scratch (__device__ globals; allocation-free rule)
__device__ float g_h1[(size_t)B_ROWS * H_DIM];
__device__ float g_h2[(size_t)B_ROWS * H_DIM];
// Transposed + 3-way bf16-split weights: planes [h, m, l], each [N, K]
__device__ __align__(16) __nv_bfloat16 g_w0t[3ull * H_DIM * D_IN];
__device__ __align__(16) __nv_bfloat16 g_w1t[3ull * H_DIM * H_DIM];
__device__ __align__(16) __nv_bfloat16 g_wlt[3ull * L_DIM * H_DIM];

// Accurate libdevice entry points (immune to fast-math remapping)
extern "C" {
__device__ float __nv_logf(float);
__device__ float __nv_log1pf(float);
__device__ float __nv_expf(float);
}

// ---------------------------------------------------------------------------
// Helpers
// ---------------------------------------------------------------------------
__device__ __forceinline__ unsigned smem_u32(const void* p) {
    unsigned a;
    asm("{ .reg .u64 t; cvta.to.shared.u64 t, %1; cvt.u32.u64 %0, t; }"
        : "=r"(a) : "l"(p));
    return a;
}
__device__ __forceinline__ unsigned pk_bf2(__nv_bfloat16 lo, __nv_bfloat16 hi) {
    return ((unsigned)__bfloat16_as_ushort(hi) << 16) |
           (unsigned)__bfloat16_as_ushort(lo);
}
// bf16x3 split: a ~= h + m + l, residual <= ~2^-25 * |a|
__device__ __forceinline__ void split3(float a, __nv_bfloat16& h,
                                       __nv_bfloat16& m, __nv_bfloat16& l) {
    h = __float2bfloat16_rn(a);
    float r = a - __bfloat162float(h);
    m = __float2bfloat16_rn(r);
    float s = r - __bfloat162float(m);
    l = __float2bfloat16_rn(s);
}
__device__ __forceinline__ void ldsm_x4(unsigned* r, unsigned addr) {
    asm volatile(
        "ldmatrix.sync.aligned.m8n8.x4.shared.b16 {%0,%1,%2,%3}, [%4];"
        : "=r"(r[0]), "=r"(r[1]), "=r"(r[2]), "=r"(r[3]) : "r"(addr));
}
__device__ __forceinline__ void mma16816(float* c, const unsigned* a,
                                         const unsigned* b) {
    asm volatile(
        "mma.sync.aligned.m16n8k16.row.col.f32.bf16.bf16.f32 "
        "{%0,%1,%2,%3}, {%4,%5,%6,%7}, {%8,%9}, {%0,%1,%2,%3};"
        : "+f"(c[0]), "+f"(c[1]), "+f"(c[2]), "+f"(c[3])
        : "r"(a[0]), "r"(a[1]), "r"(a[2]), "r"(a[3]), "r"(b[0]), "r"(b[1]));
}
#define CP_ASYNC16(dst, src) \
    asm volatile("cp.async.ca.shared.global [%0], [%1], 16;" :: "r"(dst), "l"(src))
#define CP_COMMIT()  asm volatile("cp.async.commit_group;" ::: "memory")
#define CP_WAIT0()   asm volatile("cp.async.wait_group 0;" ::: "memory")

// ---------------------------------------------------------------------------
// Weight transpose + bf16x3 split: W[K,N] -> planes [h,m,l] each [N,K]
// ---------------------------------------------------------------------------
__global__ void transpose_split_kernel(const float* __restrict__ W,
                                       __nv_bfloat16* __restrict__ T,
                                       int K, int N) {
    __shared__ float tile[32][33];
    int n0 = blockIdx.x * 32, k0 = blockIdx.y * 32;
    int tx = threadIdx.x, ty = threadIdx.y;  // 32 x 8
#pragma unroll
    for (int i = 0; i < 32; i += 8)
        tile[ty + i][tx] = W[(size_t)(k0 + ty + i) * N + n0 + tx];
    __syncthreads();
    size_t NK = (size_t)N * K;
#pragma unroll
    for (int i = 0; i < 32; i += 8) {
        float v = tile[tx][ty + i];
        __nv_bfloat16 h, m, l;
        split3(v, h, m, l);
        size_t o = (size_t)(n0 + ty + i) * K + k0 + tx;
        T[o] = h; T[NK + o] = m; T[2 * NK + o] = l;
    }
}

// ---------------------------------------------------------------------------
// Emulated-fp32 GEMM on legacy bf16 mma.sync:
//   C[M,N] = act(A[M,K] @ W[K,N] + bias)
// Ootomo-style split accumulators:
//   accH <- hh only                (alignment loss ~2^-24*|s| x 64 adds)
//   accL <- hm+mh+mm+hl+lh        (|accL| ~ 2^-8*|s| => tiny alignment loss)
//   result = accH + accL
// BM=128, BK=64, 512 threads (16 warps, 4x4), double-buffered cp.async.
// ACT: 1 = relu, 2 = softplus + 0.5
// ---------------------------------------------------------------------------
template <int BN, int ACT>
__global__ void __launch_bounds__(512, 1)
gemm_mma(const float* __restrict__ A, const __nv_bfloat16* __restrict__ Bt,
         const float* __restrict__ bias, float* __restrict__ C, int K, int N) {
    constexpr int BM = 128, BK = 64;
    constexpr int NT  = BN / 32;        // n-tiles (8 wide) per warp: 4 or 2
    constexpr int WTN = BN / 4;         // warp tile width in n
    constexpr int APLANE = BM * 128;    // bytes per A plane
    constexpr int BPLANE = BN * 128;
    constexpr int STAGE  = 3 * APLANE + 3 * BPLANE;
    extern __shared__ char smem[];
    const unsigned sm0 = smem_u32(smem);
    const int tid = threadIdx.x, wid = tid >> 5, lane = tid & 31;
    const int wm = wid & 3, wn = wid >> 2;
    const int row0 = blockIdx.y * BM, col0 = blockIdx.x * BN;
    const size_t NKe = (size_t)N * K;

    float accH[2][NT][4], accL[2][NT][4];
#pragma unroll
    for (int i = 0; i < 2; i++)
#pragma unroll
        for (int j = 0; j < NT; j++)
#pragma unroll
            for (int q = 0; q < 4; q++) { accH[i][j][q] = 0.0f; accL[i][j][q] = 0.0f; }

    float aregs[16];   // prefetched A fp32 (2 tasks x 8 elems)

    auto loadA = [&](int kt) {
#pragma unroll
        for (int i = 0; i < 2; i++) {                  // BM*8 tasks / 512
            int t = tid + i * 512;
            int r = t >> 3, ch = t & 7;
            const float* p = A + (size_t)(row0 + r) * K + kt * BK + ch * 8;
            float4 v0 = *(const float4*)p;
            float4 v1 = *(const float4*)(p + 4);
            aregs[i * 8 + 0] = v0.x; aregs[i * 8 + 1] = v0.y;
            aregs[i * 8 + 2] = v0.z; aregs[i * 8 + 3] = v0.w;
            aregs[i * 8 + 4] = v1.x; aregs[i * 8 + 5] = v1.y;
            aregs[i * 8 + 6] = v1.z; aregs[i * 8 + 7] = v1.w;
        }
    };
    auto storeA = [&](int buf) {
        char* base = smem + buf * STAGE;
#pragma unroll
        for (int i = 0; i < 2; i++) {
            int t = tid + i * 512;
            int r = t >> 3, ch = t & 7;
            unsigned off = r * 128 + ((ch ^ (r & 7)) << 4);
            unsigned hv[4], mv[4], lv[4];
#pragma unroll
            for (int j = 0; j < 4; j++) {
                __nv_bfloat16 h0, m0, l0, h1, m1, l1;
                split3(aregs[i * 8 + j * 2],     h0, m0, l0);
                split3(aregs[i * 8 + j * 2 + 1], h1, m1, l1);
                hv[j] = pk_bf2(h0, h1); mv[j] = pk_bf2(m0, m1);
                lv[j] = pk_bf2(l0, l1);
            }
            *(uint4*)(base + off)              = make_uint4(hv[0], hv[1], hv[2], hv[3]);
            *(uint4*)(base + APLANE + off)     = make_uint4(mv[0], mv[1], mv[2], mv[3]);
            *(uint4*)(base + 2 * APLANE + off) = make_uint4(lv[0], lv[1], lv[2], lv[3]);
        }
    };
    auto cpasyncB = [&](int kt, int buf) {
        constexpr int ITB = BN * 24 / 512;             // 6 or 3
#pragma unroll
        for (int i = 0; i < ITB; i++) {
            int t = tid + i * 512;
            int p  = t / (BN * 8);
            int t2 = t % (BN * 8);
            int r = t2 >> 3, ch = t2 & 7;
            const __nv_bfloat16* src =
                Bt + (size_t)p * NKe + (size_t)(col0 + r) * K + kt * BK + ch * 8;
            unsigned dst = sm0 + buf * STAGE + 3 * APLANE + p * BPLANE +
                           r * 128 + ((ch ^ (r & 7)) << 4);
            CP_ASYNC16(dst, src);
        }
    };
    auto compute = [&](int buf) {
        const unsigned abase = sm0 + buf * STAGE;
        const unsigned bbase = abase + 3 * APLANE;
#pragma unroll
        for (int ks = 0; ks < 4; ks++) {               // BK/16 k-steps
#pragma unroll
            for (int mt = 0; mt < 2; mt++) {
                unsigned af[3][4];
                {
                    int r  = wm * 32 + mt * 16 + (lane & 15);
                    int ch = ks * 2 + (lane >> 4);
                    unsigned addr = abase + r * 128 + ((ch ^ (r & 7)) << 4);
#pragma unroll
                    for (int p = 0; p < 3; p++) ldsm_x4(af[p], addr + p * APLANE);
                }
#pragma unroll
                for (int np = 0; np < NT / 2; np++) {  // ldsm.x4 covers 2 n-tiles
                    unsigned bq[3][4];
                    {
                        int r  = wn * WTN + np * 16 + ((lane >> 4) << 3) + (lane & 7);
                        int ch = ks * 2 + ((lane >> 3) & 1);
                        unsigned addr = bbase + r * 128 + ((ch ^ (r & 7)) << 4);
#pragma unroll
                        for (int p = 0; p < 3; p++) ldsm_x4(bq[p], addr + p * BPLANE);
                    }
#pragma unroll
                    for (int half = 0; half < 2; half++) {
                        const int nt = np * 2 + half;
                        unsigned bh[2] = {bq[0][half * 2], bq[0][half * 2 + 1]};
                        unsigned bm[2] = {bq[1][half * 2], bq[1][half * 2 + 1]};
                        unsigned bl[2] = {bq[2][half * 2], bq[2][half * 2 + 1]};
                        mma16816(accH[mt][nt], af[0], bh);   // hh  (isolated)
                        mma16816(accL[mt][nt], af[0], bm);   // hm
                        mma16816(accL[mt][nt], af[1], bh);   // mh
                        mma16816(accL[mt][nt], af[1], bm);   // mm
                        mma16816(accL[mt][nt], af[0], bl);   // hl
                        mma16816(accL[mt][nt], af[2], bh);   // lh
                    }
                }
            }
        }
    };

    // prologue
    loadA(0);
    cpasyncB(0, 0);
    CP_COMMIT();
    storeA(0);
    CP_WAIT0();
    __syncthreads();

    const int nk = K / BK;
    for (int kt = 0; kt < nk; kt++) {
        const int buf = kt & 1;
        if (kt + 1 < nk) { loadA(kt + 1); cpasyncB(kt + 1, buf ^ 1); CP_COMMIT(); }
        compute(buf);
        if (kt + 1 < nk) { storeA(buf ^ 1); CP_WAIT0(); }
        __syncthreads();
    }

    // epilogue: combine accumulators, bias + activation, fp32 out
#pragma unroll
    for (int mt = 0; mt < 2; mt++)
#pragma unroll
        for (int nt = 0; nt < NT; nt++) {
            int r = row0 + wm * 32 + mt * 16 + (lane >> 2);
            int c = col0 + wn * WTN + nt * 8 + (lane & 3) * 2;
            float b0 = bias[c], b1 = bias[c + 1];
            float v0 = (accH[mt][nt][0] + accL[mt][nt][0]) + b0;
            float v1 = (accH[mt][nt][1] + accL[mt][nt][1]) + b1;
            float v2 = (accH[mt][nt][2] + accL[mt][nt][2]) + b0;
            float v3 = (accH[mt][nt][3] + accL[mt][nt][3]) + b1;
            if (ACT == 1) {
                v0 = fmaxf(v0, 0.f); v1 = fmaxf(v1, 0.f);
                v2 = fmaxf(v2, 0.f); v3 = fmaxf(v3, 0.f);
            } else {
                v0 = fmaxf(v0, 0.f) + __nv_log1pf(__nv_expf(-fabsf(v0))) + 0.5f;
                v1 = fmaxf(v1, 0.f) + __nv_log1pf(__nv_expf(-fabsf(v1))) + 0.5f;
                v2 = fmaxf(v2, 0.f) + __nv_log1pf(__nv_expf(-fabsf(v2))) + 0.5f;
                v3 = fmaxf(v3, 0.f) + __nv_log1pf(__nv_expf(-fabsf(v3))) + 0.5f;
            }
            *(float2*)(C + (size_t)r * N + c)       = make_float2(v0, v1);
            *(float2*)(C + (size_t)(r + 8) * N + c) = make_float2(v2, v3);
        }
}

// ---------------------------------------------------------------------------
// threefry2x32 (JAX-exact, 20 rounds)
// ---------------------------------------------------------------------------
__host__ __device__ __forceinline__ void tf2x32(unsigned k0, unsigned k1,
                                                unsigned x0, unsigned x1,
                                                unsigned& o0, unsigned& o1) {
    unsigned ks2 = k0 ^ k1 ^ 0x1BD11BDAu;
    x0 += k0; x1 += k1;
#define TF_R(r) { x0 += x1; x1 = (x1 << (r)) | (x1 >> (32 - (r))); x1 ^= x0; }
    TF_R(13) TF_R(15) TF_R(26) TF_R(6)
    x0 += k1;  x1 += ks2 + 1u;
    TF_R(17) TF_R(29) TF_R(16) TF_R(24)
    x0 += ks2; x1 += k0 + 2u;
    TF_R(13) TF_R(15) TF_R(26) TF_R(6)
    x0 += k0;  x1 += k1 + 3u;
    TF_R(17) TF_R(29) TF_R(16) TF_R(24)
    x0 += k1;  x1 += ks2 + 4u;
    TF_R(13) TF_R(15) TF_R(26) TF_R(6)
    x0 += ks2; x1 += k0 + 5u;
#undef TF_R
    o0 = x0; o1 = x1;
}

// XLA ErfInv (Giles), unfused to mirror XLA codegen
__device__ __forceinline__ float erfinv_xla(float x) {
    float w = -__nv_log1pf(-__fmul_rn(x, x));
    float p;
    if (w < 5.0f) {
        w = __fsub_rn(w, 2.5f);
        p = 2.81022636e-08f;
        p = __fadd_rn(__fmul_rn(p, w), 3.43273939e-07f);
        p = __fadd_rn(__fmul_rn(p, w), -3.5233877e-06f);
        p = __fadd_rn(__fmul_rn(p, w), -4.39150654e-06f);
        p = __fadd_rn(__fmul_rn(p, w), 0.00021858087f);
        p = __fadd_rn(__fmul_rn(p, w), -0.00125372503f);
        p = __fadd_rn(__fmul_rn(p, w), -0.00417768164f);
        p = __fadd_rn(__fmul_rn(p, w), 0.246640727f);
        p = __fadd_rn(__fmul_rn(p, w), 1.50140941f);
    } else {
        w = __fsub_rn(__fsqrt_rn(w), 3.0f);
        p = -0.000200214257f;
        p = __fadd_rn(__fmul_rn(p, w), 0.000100950558f);
        p = __fadd_rn(__fmul_rn(p, w), 0.00134934322f);
        p = __fadd_rn(__fmul_rn(p, w), -0.00367342844f);
        p = __fadd_rn(__fmul_rn(p, w), 0.00573950773f);
        p = __fadd_rn(__fmul_rn(p, w), -0.0076224613f);
        p = __fadd_rn(__fmul_rn(p, w), 0.00943887047f);
        p = __fadd_rn(__fmul_rn(p, w), 1.00167406f);
        p = __fadd_rn(__fmul_rn(p, w), 2.83297682f);
    }
    return __fmul_rn(p, x);
}

// ---------------------------------------------------------------------------
// Marsaglia-Tsang sampler, JAX-exact randomness (threefry_partitionable)
// ---------------------------------------------------------------------------
__global__ void __launch_bounds__(256)
sampler_kernel(const float* __restrict__ alpha, float* __restrict__ outp,
               unsigned kz0, unsigned kz1, unsigned ku0, unsigned ku1) {
    int idx = blockIdx.x * 256 + threadIdx.x;
    if (idx >= NBL) return;

    const float LO = -0.99999994f;  // nextafterf(-1, 0)

    float a = alpha[idx];
    float d = __fsub_rn(a, 0.33333334f);
    float c = __fdiv_rn(1.0f, __fsqrt_rn(__fmul_rn(9.0f, d)));

    float result = 0.0f, first_s = 0.0f;
    bool done = false;

#pragma unroll 1
    for (int k = 0; k < 16; ++k) {
        unsigned cnt = (unsigned)(k * NBL + idx);

        unsigned o0, o1;
        tf2x32(kz0, kz1, 0u, cnt, o0, o1);
        unsigned bz = o0 ^ o1;
        float fz = __fsub_rn(__uint_as_float((bz >> 9) | 0x3f800000u), 1.0f);
        float un = fmaxf(LO, __fadd_rn(__fmul_rn(fz, 2.0f), LO));
        float z  = __fmul_rn(1.41421356f, erfinv_xla(un));

        float t  = __fadd_rn(1.0f, __fmul_rn(c, z));
        float v  = __fmul_rn(__fmul_rn(t, t), t);
        bool pos = v > 0.0f;
        float sv = pos ? v : 1.0f;
        float samp = __fmul_rn(d, sv);
        if (k == 0) first_s = samp;

        tf2x32(ku0, ku1, 0u, cnt, o0, o1);
        unsigned bu = o0 ^ o1;
        float fu = __fsub_rn(__uint_as_float((bu >> 9) | 0x3f800000u), 1.0f);
        float uu = fmaxf(1e-7f, __fadd_rn(__fmul_rn(fu, (1.0f - 1e-7f)), 1e-7f));

        float zz = __fmul_rn(z, z);
        float b2 = __fadd_rn(
            __fsub_rn(__fadd_rn(__fmul_rn(0.5f, zz), d), __fmul_rn(d, sv)),
            __fmul_rn(d, __nv_logf(sv)));

        if (pos && (__nv_logf(uu) < b2)) { result = samp; done = true; break; }
    }
    outp[idx] = done ? result : first_s;
}

// ---------------------------------------------------------------------------
// Launch
// ---------------------------------------------------------------------------
extern "C" void kernel_launch(void* const* d_in, const int* in_sizes, int n_in,
                              void* d_out, int out_size) {
    const float* x  = (const float*)d_in[0];
    const float* W0 = (const float*)d_in[1];
    const float* b0 = (const float*)d_in[2];
    const float* W1 = (const float*)d_in[3];
    const float* b1 = (const float*)d_in[4];
    const float* Wl = (const float*)d_in[5];
    const float* bl = (const float*)d_in[6];
    float* out = (float*)d_out;  // [alpha (B*L) | sample (B*L)]

    float *h1, *h2;
    __nv_bfloat16 *w0t, *w1t, *wlt;
    cudaGetSymbolAddress((void**)&h1, g_h1);
    cudaGetSymbolAddress((void**)&h2, g_h2);
    cudaGetSymbolAddress((void**)&w0t, g_w0t);
    cudaGetSymbolAddress((void**)&w1t, g_w1t);
    cudaGetSymbolAddress((void**)&wlt, g_wlt);

    // Weight transpose + bf16x3 split (tiny)
    transpose_split_kernel<<<dim3(H_DIM / 32, D_IN / 32), dim3(32, 8)>>>(W0, w0t, D_IN, H_DIM);
    transpose_split_kernel<<<dim3(H_DIM / 32, H_DIM / 32), dim3(32, 8)>>>(W1, w1t, H_DIM, H_DIM);
    transpose_split_kernel<<<dim3(L_DIM / 32, H_DIM / 32), dim3(32, 8)>>>(Wl, wlt, H_DIM, L_DIM);

    constexpr int APL = 128 * 128;                      // A plane bytes
    constexpr int SMEM128 = 2 * (3 * APL + 3 * 128 * 128);  // 196608
    constexpr int SMEM64  = 2 * (3 * APL + 3 * 64 * 128);   // 147456
    cudaFuncSetAttribute(gemm_mma<128, 1>, cudaFuncAttributeMaxDynamicSharedMemorySize, SMEM128);
    cudaFuncSetAttribute(gemm_mma<64, 2>,  cudaFuncAttributeMaxDynamicSharedMemorySize, SMEM64);

    gemm_mma<128, 1><<<dim3(H_DIM / 128, B_ROWS / 128), 512, SMEM128>>>(x,  w0t, b0, h1, D_IN,  H_DIM);
    gemm_mma<128, 1><<<dim3(H_DIM / 128, B_ROWS / 128), 512, SMEM128>>>(h1, w1t, b1, h2, H_DIM, H_DIM);
    gemm_mma<64, 2><<<dim3(1, B_ROWS / 128), 512, SMEM64>>>(h2, wlt, bl, out, H_DIM, L_DIM);

    // fold-like split of key(1) = (0,1): kz = cipher(key;0,0), ku = cipher(key;0,1)
    unsigned kz0, kz1, ku0, ku1;
    tf2x32(0u, 1u, 0u, 0u, kz0, kz1);
    tf2x32(0u, 1u, 0u, 1u, ku0, ku1);

    sampler_kernel<<<NBL / 256, 256>>>(out, out + NBL, kz0, kz1, ku0, ku1);
}